// round 3
// baseline (speedup 1.0000x reference)
#include <cuda_runtime.h>
#include <cstdint>

// ---------------------------------------------------------------------------
// PrefilledAttention: B=8, S=2048, D=1024, R=128
//
// Pipeline (all GEMMs K-major x K-major, conflict-free smem):
//   K1: q3 = x @ Wq^T, epilogue splits to [hi | lo | hi]   (3xTF32 via K-trip)
//   K2: k3 = x @ Wk^T, epilogue splits to [hi | hi | lo]
//   K3: vT = Wv @ x^T, epilogue rounds to tf32             [1024, 16384]
//   K4: s  = q3 @ k3^T * 1/sqrt(128)  (plain tf32, K=384 == 3x compensated)
//   K5: softmax rows in place, rounds probs to tf32
//   K6: out = probs @ v  ==  A=probs, B=vT (K-major)
// Consumers of pre-rounded data skip cvt entirely (bits already tf32).
// ---------------------------------------------------------------------------

#define BATCH 8
#define SEQ   2048
#define DIM   1024
#define RANK  128

#define BM 128
#define BN 128
#define BK 32
#define NTHREADS 256

// Scratch (allocation-free rule: __device__ globals)
__device__ float g_q3[(size_t)BATCH * SEQ * 3 * RANK];     // 25 MB
__device__ float g_k3[(size_t)BATCH * SEQ * 3 * RANK];     // 25 MB
__device__ float g_vT[(size_t)DIM * BATCH * SEQ];          // 64 MB  [D, B*S]
__device__ float g_s [(size_t)BATCH * SEQ * SEQ];          // 128 MB

// ---------------------------------------------------------------------------
__device__ __forceinline__ uint32_t tf32_of(float v) {
    uint32_t r;
    asm("cvt.rna.tf32.f32 %0, %1;" : "=r"(r) : "f"(v));
    return r;
}
__device__ __forceinline__ float tf32_round(float v) {
    return __uint_as_float(tf32_of(v));
}

__device__ __forceinline__ void cp_async16(void* smem, const void* gmem) {
    uint32_t s = (uint32_t)__cvta_generic_to_shared(smem);
    asm volatile("cp.async.cg.shared.global [%0], [%1], 16;\n" :: "r"(s), "l"(gmem));
}
__device__ __forceinline__ void cp_commit() {
    asm volatile("cp.async.commit_group;\n");
}
template <int N>
__device__ __forceinline__ void cp_wait() {
    asm volatile("cp.async.wait_group %0;\n" :: "n"(N));
}

__device__ __forceinline__ void mma_tf32(float* c, const uint32_t* a, const uint32_t* b) {
    asm volatile(
        "mma.sync.aligned.m16n8k8.row.col.f32.tf32.tf32.f32 "
        "{%0,%1,%2,%3}, {%4,%5,%6,%7}, {%8,%9}, {%0,%1,%2,%3};"
        : "+f"(c[0]), "+f"(c[1]), "+f"(c[2]), "+f"(c[3])
        : "r"(a[0]), "r"(a[1]), "r"(a[2]), "r"(a[3]), "r"(b[0]), "r"(b[1]));
}

// ---------------------------------------------------------------------------
// Tiled GEMM:  C[M,N] = alpha * A[M,K] * B^T   (B is [N,K], K contiguous)
//   CVT : convert fp32 -> tf32 in the inner loop (raw-fp32 operands)
//   X3  : 3xTF32 hi/lo split in-kernel (q/k projections only; implies CVT)
//   MODE: 0 = plain store, 1 = q3 split store [hi|lo|hi],
//         2 = k3 split store [hi|hi|lo], 3 = tf32-rounded store
//   lda/ldb/ldc are row strides; aS/bS/cS per-batch offsets (blockIdx.z).
// ---------------------------------------------------------------------------
template <bool CVT, bool X3, int MODE>
__global__ void __launch_bounds__(NTHREADS, CVT ? 1 : 2)
gemm_kernel(const float* __restrict__ A, const float* __restrict__ Bm,
            float* __restrict__ C, int M, int N, int K,
            int lda, int ldb, int ldc,
            long aS, long bS, long cS, float alpha)
{
    constexpr int ST  = 36;                 // padded smem stride (floats)
    constexpr int TSZ = 128 * ST;           // one 128x32 tile
    constexpr int STAGE = 2 * TSZ;          // A + B tile

    extern __shared__ float sm[];

    const float* Ab = A  + (long)blockIdx.z * aS;
    const float* Bb = Bm + (long)blockIdx.z * bS;
    float*       Cb = C  + (long)blockIdx.z * cS;

    const int bm = blockIdx.y * BM;
    const int bn = blockIdx.x * BN;
    const int tid = threadIdx.x;

    const int row8 = tid >> 3;            // 0..31
    const int col4 = (tid & 7) * 4;       // 16B granularity

    auto load_tile = [&](int kt, int stage) {
        float* As = sm + stage * STAGE;
        float* Bs = As + TSZ;
        const float* Ag = Ab + (size_t)bm * lda + kt * BK;
        const float* Bg = Bb + (size_t)bn * ldb + kt * BK;
#pragma unroll
        for (int i = 0; i < 4; i++) {
            int r = row8 + i * 32;
            cp_async16(&As[r * ST + col4], Ag + (size_t)r * lda + col4);
            cp_async16(&Bs[r * ST + col4], Bg + (size_t)r * ldb + col4);
        }
    };

    // warp/fragment indexing
    const int lane = tid & 31;
    const int warp = tid >> 5;
    const int wm = warp & 1;          // 2 warps along M
    const int wn = warp >> 1;         // 4 warps along N
    const int g  = lane >> 2;         // 0..7
    const int tg = lane & 3;          // 0..3

    float acc[4][4][4];
#pragma unroll
    for (int a = 0; a < 4; a++)
#pragma unroll
        for (int b = 0; b < 4; b++)
#pragma unroll
            for (int c = 0; c < 4; c++) acc[a][b][c] = 0.f;

    const int KT = K / BK;
    load_tile(0, 0);
    cp_commit();

    for (int kt = 0; kt < KT; kt++) {
        if (kt + 1 < KT) {
            load_tile(kt + 1, (kt + 1) & 1);
            cp_commit();
            cp_wait<1>();
        } else {
            cp_wait<0>();
        }
        __syncthreads();

        const float* As = sm + (kt & 1) * STAGE;
        const float* Bs = As + TSZ;

#pragma unroll
        for (int ks = 0; ks < 4; ks++) {
            const int kk = ks * 8;

            uint32_t ahi[4][4], alo[4][4];
#pragma unroll
            for (int mf = 0; mf < 4; mf++) {
                int r0 = wm * 64 + mf * 16 + g;
                float v0 = As[r0 * ST + kk + tg];
                float v1 = As[(r0 + 8) * ST + kk + tg];
                float v2 = As[r0 * ST + kk + tg + 4];
                float v3 = As[(r0 + 8) * ST + kk + tg + 4];
                if (CVT) {
                    ahi[mf][0] = tf32_of(v0);
                    ahi[mf][1] = tf32_of(v1);
                    ahi[mf][2] = tf32_of(v2);
                    ahi[mf][3] = tf32_of(v3);
                } else {
                    ahi[mf][0] = __float_as_uint(v0);
                    ahi[mf][1] = __float_as_uint(v1);
                    ahi[mf][2] = __float_as_uint(v2);
                    ahi[mf][3] = __float_as_uint(v3);
                }
                if (X3) {
                    alo[mf][0] = tf32_of(v0 - __uint_as_float(ahi[mf][0]));
                    alo[mf][1] = tf32_of(v1 - __uint_as_float(ahi[mf][1]));
                    alo[mf][2] = tf32_of(v2 - __uint_as_float(ahi[mf][2]));
                    alo[mf][3] = tf32_of(v3 - __uint_as_float(ahi[mf][3]));
                }
            }

            uint32_t bhi[4][2], blo[4][2];
#pragma unroll
            for (int nf = 0; nf < 4; nf++) {
                int n = wn * 32 + nf * 8 + g;
                float v0 = Bs[n * ST + kk + tg];
                float v1 = Bs[n * ST + kk + tg + 4];
                if (CVT) {
                    bhi[nf][0] = tf32_of(v0);
                    bhi[nf][1] = tf32_of(v1);
                } else {
                    bhi[nf][0] = __float_as_uint(v0);
                    bhi[nf][1] = __float_as_uint(v1);
                }
                if (X3) {
                    blo[nf][0] = tf32_of(v0 - __uint_as_float(bhi[nf][0]));
                    blo[nf][1] = tf32_of(v1 - __uint_as_float(bhi[nf][1]));
                }
            }

#pragma unroll
            for (int mf = 0; mf < 4; mf++)
#pragma unroll
                for (int nf = 0; nf < 4; nf++) {
                    if (X3) {
                        mma_tf32(acc[mf][nf], alo[mf], bhi[nf]);
                        mma_tf32(acc[mf][nf], ahi[mf], blo[nf]);
                    }
                    mma_tf32(acc[mf][nf], ahi[mf], bhi[nf]);
                }
        }
        __syncthreads();
    }

    // ---- epilogue ----
#pragma unroll
    for (int mf = 0; mf < 4; mf++) {
        int r0 = bm + wm * 64 + mf * 16 + g;
#pragma unroll
        for (int nf = 0; nf < 4; nf++) {
            int c0 = bn + wn * 32 + nf * 8 + tg * 2;
            float x0 = acc[mf][nf][0] * alpha;
            float x1 = acc[mf][nf][1] * alpha;
            float x2 = acc[mf][nf][2] * alpha;
            float x3 = acc[mf][nf][3] * alpha;
            if (MODE == 0) {
                *(float2*)(Cb + (size_t)r0 * ldc + c0)       = make_float2(x0, x1);
                *(float2*)(Cb + (size_t)(r0 + 8) * ldc + c0) = make_float2(x2, x3);
            } else if (MODE == 3) {
                *(float2*)(Cb + (size_t)r0 * ldc + c0) =
                    make_float2(tf32_round(x0), tf32_round(x1));
                *(float2*)(Cb + (size_t)(r0 + 8) * ldc + c0) =
                    make_float2(tf32_round(x2), tf32_round(x3));
            } else {
                // hi/lo split store: q3 layout [hi|lo|hi], k3 layout [hi|hi|lo]
                float h0 = tf32_round(x0), h1 = tf32_round(x1);
                float h2 = tf32_round(x2), h3 = tf32_round(x3);
                float l0 = tf32_round(x0 - h0), l1 = tf32_round(x1 - h1);
                float l2 = tf32_round(x2 - h2), l3 = tf32_round(x3 - h3);
                int c_hi2 = (MODE == 1) ? c0 + 2 * RANK : c0 + RANK;
                int c_lo  = (MODE == 1) ? c0 + RANK     : c0 + 2 * RANK;
                *(float2*)(Cb + (size_t)r0 * ldc + c0)          = make_float2(h0, h1);
                *(float2*)(Cb + (size_t)(r0 + 8) * ldc + c0)    = make_float2(h2, h3);
                *(float2*)(Cb + (size_t)r0 * ldc + c_hi2)       = make_float2(h0, h1);
                *(float2*)(Cb + (size_t)(r0 + 8) * ldc + c_hi2) = make_float2(h2, h3);
                *(float2*)(Cb + (size_t)r0 * ldc + c_lo)        = make_float2(l0, l1);
                *(float2*)(Cb + (size_t)(r0 + 8) * ldc + c_lo)  = make_float2(l2, l3);
            }
        }
    }
}

// ---------------------------------------------------------------------------
// Row softmax, in place, rounds probs to tf32. One CTA per row of 2048.
// ---------------------------------------------------------------------------
__global__ void __launch_bounds__(256) softmax_kernel(float* __restrict__ S)
{
    float4* row = (float4*)(S + (size_t)blockIdx.x * SEQ);
    const int tid = threadIdx.x;

    float4 a = row[tid];
    float4 b = row[tid + 256];

    float m = fmaxf(fmaxf(fmaxf(a.x, a.y), fmaxf(a.z, a.w)),
                    fmaxf(fmaxf(b.x, b.y), fmaxf(b.z, b.w)));

    __shared__ float red[8];
#pragma unroll
    for (int o = 16; o; o >>= 1) m = fmaxf(m, __shfl_xor_sync(0xffffffffu, m, o));
    if ((tid & 31) == 0) red[tid >> 5] = m;
    __syncthreads();
    m = red[0];
#pragma unroll
    for (int i = 1; i < 8; i++) m = fmaxf(m, red[i]);
    __syncthreads();

    a.x = __expf(a.x - m); a.y = __expf(a.y - m);
    a.z = __expf(a.z - m); a.w = __expf(a.w - m);
    b.x = __expf(b.x - m); b.y = __expf(b.y - m);
    b.z = __expf(b.z - m); b.w = __expf(b.w - m);

    float s = a.x + a.y + a.z + a.w + b.x + b.y + b.z + b.w;
#pragma unroll
    for (int o = 16; o; o >>= 1) s += __shfl_xor_sync(0xffffffffu, s, o);
    if ((tid & 31) == 0) red[tid >> 5] = s;
    __syncthreads();
    float tot = red[0];
#pragma unroll
    for (int i = 1; i < 8; i++) tot += red[i];

    float inv = 1.0f / tot;
    a.x = tf32_round(a.x * inv); a.y = tf32_round(a.y * inv);
    a.z = tf32_round(a.z * inv); a.w = tf32_round(a.w * inv);
    b.x = tf32_round(b.x * inv); b.y = tf32_round(b.y * inv);
    b.z = tf32_round(b.z * inv); b.w = tf32_round(b.w * inv);

    row[tid]       = a;
    row[tid + 256] = b;
}

// ---------------------------------------------------------------------------
// launch
// ---------------------------------------------------------------------------
extern "C" void kernel_launch(void* const* d_in, const int* in_sizes, int n_in,
                              void* d_out, int out_size)
{
    (void)in_sizes; (void)n_in; (void)out_size;
    const float* x  = (const float*)d_in[0];
    const float* Wq = (const float*)d_in[1];
    const float* Wk = (const float*)d_in[2];
    const float* Wv = (const float*)d_in[3];
    float* out = (float*)d_out;

    void *pq, *pk, *pv, *ps;
    cudaGetSymbolAddress(&pq, g_q3);
    cudaGetSymbolAddress(&pk, g_k3);
    cudaGetSymbolAddress(&pv, g_vT);
    cudaGetSymbolAddress(&ps, g_s);
    float* q3 = (float*)pq;
    float* k3 = (float*)pk;
    float* vT = (float*)pv;
    float* s  = (float*)ps;

    const int SMEM = 2 * (2 * 128 * 36) * 4;   // 73728 B

    cudaFuncSetAttribute((const void*)gemm_kernel<true,  true,  1>,
                         cudaFuncAttributeMaxDynamicSharedMemorySize, SMEM);
    cudaFuncSetAttribute((const void*)gemm_kernel<true,  true,  2>,
                         cudaFuncAttributeMaxDynamicSharedMemorySize, SMEM);
    cudaFuncSetAttribute((const void*)gemm_kernel<true,  false, 3>,
                         cudaFuncAttributeMaxDynamicSharedMemorySize, SMEM);
    cudaFuncSetAttribute((const void*)gemm_kernel<false, false, 0>,
                         cudaFuncAttributeMaxDynamicSharedMemorySize, SMEM);

    const int MT = BATCH * SEQ;               // 16384 flattened tokens
    const int R3 = 3 * RANK;                  // 384
    const float scale = 0.08838834764831845f; // 1/sqrt(128)

    // K1: q3 = split(x @ Wq^T)   [MT, 384] layout [hi|lo|hi]
    gemm_kernel<true, true, 1><<<dim3(1, MT / BM, 1), NTHREADS, SMEM>>>(
        x, Wq, q3, MT, RANK, DIM, DIM, DIM, R3, 0, 0, 0, 1.f);
    // K2: k3 = split(x @ Wk^T)   [MT, 384] layout [hi|hi|lo]
    gemm_kernel<true, true, 2><<<dim3(1, MT / BM, 1), NTHREADS, SMEM>>>(
        x, Wk, k3, MT, RANK, DIM, DIM, DIM, R3, 0, 0, 0, 1.f);
    // K3: vT = round(Wv @ x^T)   [DIM, MT]
    gemm_kernel<true, false, 3><<<dim3(MT / BN, DIM / BM, 1), NTHREADS, SMEM>>>(
        Wv, x, vT, DIM, MT, DIM, DIM, DIM, MT, 0, 0, 0, 1.f);
    // K4: s = q3 @ k3^T * scale  (plain tf32 == 3x compensated, batched)
    gemm_kernel<false, false, 0><<<dim3(SEQ / BN, SEQ / BM, BATCH), NTHREADS, SMEM>>>(
        q3, k3, s, SEQ, SEQ, R3, R3, R3, SEQ,
        (long)SEQ * R3, (long)SEQ * R3, (long)SEQ * SEQ, scale);
    // K5: softmax rows (in place, rounds to tf32)
    softmax_kernel<<<BATCH * SEQ, 256>>>(s);
    // K6: out = probs @ v  ==  A=probs [S,S], B=vT rows (K-major), batched
    gemm_kernel<false, false, 0><<<dim3(DIM / BN, SEQ / BM, BATCH), NTHREADS, SMEM>>>(
        s, vT, out, SEQ, DIM, SEQ, SEQ, MT, DIM,
        (long)SEQ * SEQ, (long)SEQ, (long)SEQ * DIM, 1.f);
}

// round 4
// speedup vs baseline: 1.0809x; 1.0809x over previous
#include <cuda_runtime.h>
#include <cstdint>

// ---------------------------------------------------------------------------
// PrefilledAttention: B=8, S=2048, D=1024, R=128
//
// Pipeline (all GEMMs K-major x K-major, conflict-free smem, ldmatrix frags):
//   K1: q3 = x @ Wq^T, epilogue splits to [hi | lo | hi]   (3xTF32 via K-trip)
//   K2: k3 = x @ Wk^T, epilogue splits to [hi | hi | lo]
//   K3: vT = Wv @ x^T, epilogue rounds to tf32             [1024, 16384]
//   K4: s  = q3 @ k3^T * 1/sqrt(128)  (plain tf32, K=384 == 3x compensated)
//   K5: softmax rows in place, rounds probs to tf32
//   K6: out = probs @ v  ==  A=probs, B=vT (K-major)
// R3 ncu: scalar-LDS fragment loads capped tensor pipe at 50%. This round all
// fragment loads go through ldmatrix.m8n8.x4 (8x4 fp32 tile == 8x8 b16 tile,
// lane map matches m16n8k8 operand layout exactly): 24 LDS -> 6 LDSM per
// k-slice per warp.
// ---------------------------------------------------------------------------

#define BATCH 8
#define SEQ   2048
#define DIM   1024
#define RANK  128

#define BM 128
#define BN 128
#define BK 32
#define NTHREADS 256

// Scratch (allocation-free rule: __device__ globals)
__device__ float g_q3[(size_t)BATCH * SEQ * 3 * RANK];     // 25 MB
__device__ float g_k3[(size_t)BATCH * SEQ * 3 * RANK];     // 25 MB
__device__ float g_vT[(size_t)DIM * BATCH * SEQ];          // 64 MB  [D, B*S]
__device__ float g_s [(size_t)BATCH * SEQ * SEQ];          // 128 MB

// ---------------------------------------------------------------------------
__device__ __forceinline__ uint32_t tf32_of(float v) {
    uint32_t r;
    asm("cvt.rna.tf32.f32 %0, %1;" : "=r"(r) : "f"(v));
    return r;
}
__device__ __forceinline__ float tf32_round(float v) {
    return __uint_as_float(tf32_of(v));
}

__device__ __forceinline__ void cp_async16(void* smem, const void* gmem) {
    uint32_t s = (uint32_t)__cvta_generic_to_shared(smem);
    asm volatile("cp.async.cg.shared.global [%0], [%1], 16;\n" :: "r"(s), "l"(gmem));
}
__device__ __forceinline__ void cp_commit() {
    asm volatile("cp.async.commit_group;\n");
}
template <int N>
__device__ __forceinline__ void cp_wait() {
    asm volatile("cp.async.wait_group %0;\n" :: "n"(N));
}

__device__ __forceinline__ void ldsm4(uint32_t& d0, uint32_t& d1,
                                      uint32_t& d2, uint32_t& d3, uint32_t addr) {
    asm volatile("ldmatrix.sync.aligned.m8n8.x4.shared.b16 {%0,%1,%2,%3}, [%4];"
                 : "=r"(d0), "=r"(d1), "=r"(d2), "=r"(d3) : "r"(addr));
}

__device__ __forceinline__ void mma_tf32(float* c, const uint32_t* a, const uint32_t* b) {
    asm volatile(
        "mma.sync.aligned.m16n8k8.row.col.f32.tf32.tf32.f32 "
        "{%0,%1,%2,%3}, {%4,%5,%6,%7}, {%8,%9}, {%0,%1,%2,%3};"
        : "+f"(c[0]), "+f"(c[1]), "+f"(c[2]), "+f"(c[3])
        : "r"(a[0]), "r"(a[1]), "r"(a[2]), "r"(a[3]), "r"(b[0]), "r"(b[1]));
}

// ---------------------------------------------------------------------------
// Tiled GEMM:  C[M,N] = alpha * A[M,K] * B^T   (B is [N,K], K contiguous)
//   CVT : convert fp32 -> tf32 on loaded fragments (raw-fp32 operands)
//   X3  : 3xTF32 hi/lo split in-kernel (q/k projections only; implies CVT)
//   MODE: 0 = plain store, 1 = q3 split store [hi|lo|hi],
//         2 = k3 split store [hi|hi|lo], 3 = tf32-rounded store
// ---------------------------------------------------------------------------
template <bool CVT, bool X3, int MODE>
__global__ void __launch_bounds__(NTHREADS, CVT ? 1 : 2)
gemm_kernel(const float* __restrict__ A, const float* __restrict__ Bm,
            float* __restrict__ C, int M, int N, int K,
            int lda, int ldb, int ldc,
            long aS, long bS, long cS, float alpha)
{
    constexpr int ST  = 36;                 // padded smem stride (floats)
    constexpr int TSZ = 128 * ST;           // one 128x32 tile (floats)
    constexpr int STAGE = 2 * TSZ;          // A + B tile (floats)
    constexpr int STAGE_B = STAGE * 4;      // bytes

    extern __shared__ float sm[];

    const float* Ab = A  + (long)blockIdx.z * aS;
    const float* Bb = Bm + (long)blockIdx.z * bS;
    float*       Cb = C  + (long)blockIdx.z * cS;

    const int bm = blockIdx.y * BM;
    const int bn = blockIdx.x * BN;
    const int tid = threadIdx.x;

    const int row8 = tid >> 3;            // 0..31
    const int col4 = (tid & 7) * 4;       // 16B granularity

    auto load_tile = [&](int kt, int stage) {
        float* As = sm + stage * STAGE;
        float* Bs = As + TSZ;
        const float* Ag = Ab + (size_t)bm * lda + kt * BK;
        const float* Bg = Bb + (size_t)bn * ldb + kt * BK;
#pragma unroll
        for (int i = 0; i < 4; i++) {
            int r = row8 + i * 32;
            cp_async16(&As[r * ST + col4], Ag + (size_t)r * lda + col4);
            cp_async16(&Bs[r * ST + col4], Bg + (size_t)r * ldb + col4);
        }
    };

    // warp/fragment indexing
    const int lane = tid & 31;
    const int warp = tid >> 5;
    const int wm = warp & 1;          // 2 warps along M
    const int wn = warp >> 1;         // 4 warps along N
    const int g  = lane >> 2;         // 0..7
    const int tg = lane & 3;          // 0..3

    // ldmatrix per-lane byte offsets (within a stage).
    // A x4 (per mf): m0 rows g+0..7 col kk, m1 rows +8, m2 col kk+4, m3 rows+8 col+4
    const uint32_t sbase = (uint32_t)__cvta_generic_to_shared(sm);
    const uint32_t a_off = ((wm * 64 + (lane & 7) + ((lane >> 3) & 1) * 8) * ST
                            + (lane >> 4) * 4) * 4;
    // B x4 (per nf-pair): m0 nf rows col kk, m1 col kk+4, m2 nf+1 rows, m3 nf+1 col+4
    const uint32_t b_off = ((wn * 32 + (lane >> 4) * 8 + (lane & 7)) * ST
                            + ((lane >> 3) & 1) * 4) * 4 + TSZ * 4;

    float acc[4][4][4];
#pragma unroll
    for (int a = 0; a < 4; a++)
#pragma unroll
        for (int b = 0; b < 4; b++)
#pragma unroll
            for (int c = 0; c < 4; c++) acc[a][b][c] = 0.f;

    const int KT = K / BK;
    load_tile(0, 0);
    cp_commit();

    for (int kt = 0; kt < KT; kt++) {
        if (kt + 1 < KT) {
            load_tile(kt + 1, (kt + 1) & 1);
            cp_commit();
            cp_wait<1>();
        } else {
            cp_wait<0>();
        }
        __syncthreads();

        const uint32_t stg = sbase + (kt & 1) * STAGE_B;
        const uint32_t aA = stg + a_off;
        const uint32_t aB = stg + b_off;

#pragma unroll
        for (int ks = 0; ks < 4; ks++) {
            const uint32_t ksb = ks * 32;   // 8 floats

            uint32_t ahi[4][4], alo[4][4];
#pragma unroll
            for (int mf = 0; mf < 4; mf++) {
                ldsm4(ahi[mf][0], ahi[mf][1], ahi[mf][2], ahi[mf][3],
                      aA + mf * (16 * ST * 4) + ksb);
                if (CVT) {
#pragma unroll
                    for (int i = 0; i < 4; i++) {
                        float v = __uint_as_float(ahi[mf][i]);
                        ahi[mf][i] = tf32_of(v);
                        if (X3)
                            alo[mf][i] = tf32_of(v - __uint_as_float(ahi[mf][i]));
                    }
                }
            }

            uint32_t bhi[4][2], blo[4][2];
            ldsm4(bhi[0][0], bhi[0][1], bhi[1][0], bhi[1][1], aB + ksb);
            ldsm4(bhi[2][0], bhi[2][1], bhi[3][0], bhi[3][1],
                  aB + (16 * ST * 4) + ksb);
            if (CVT) {
#pragma unroll
                for (int nf = 0; nf < 4; nf++)
#pragma unroll
                    for (int i = 0; i < 2; i++) {
                        float v = __uint_as_float(bhi[nf][i]);
                        bhi[nf][i] = tf32_of(v);
                        if (X3)
                            blo[nf][i] = tf32_of(v - __uint_as_float(bhi[nf][i]));
                    }
            }

#pragma unroll
            for (int mf = 0; mf < 4; mf++)
#pragma unroll
                for (int nf = 0; nf < 4; nf++) {
                    if (X3) {
                        mma_tf32(acc[mf][nf], alo[mf], bhi[nf]);
                        mma_tf32(acc[mf][nf], ahi[mf], blo[nf]);
                    }
                    mma_tf32(acc[mf][nf], ahi[mf], bhi[nf]);
                }
        }
        __syncthreads();
    }

    // ---- epilogue ----
#pragma unroll
    for (int mf = 0; mf < 4; mf++) {
        int r0 = bm + wm * 64 + mf * 16 + g;
#pragma unroll
        for (int nf = 0; nf < 4; nf++) {
            int c0 = bn + wn * 32 + nf * 8 + tg * 2;
            float x0 = acc[mf][nf][0] * alpha;
            float x1 = acc[mf][nf][1] * alpha;
            float x2 = acc[mf][nf][2] * alpha;
            float x3 = acc[mf][nf][3] * alpha;
            if (MODE == 0) {
                *(float2*)(Cb + (size_t)r0 * ldc + c0)       = make_float2(x0, x1);
                *(float2*)(Cb + (size_t)(r0 + 8) * ldc + c0) = make_float2(x2, x3);
            } else if (MODE == 3) {
                *(float2*)(Cb + (size_t)r0 * ldc + c0) =
                    make_float2(tf32_round(x0), tf32_round(x1));
                *(float2*)(Cb + (size_t)(r0 + 8) * ldc + c0) =
                    make_float2(tf32_round(x2), tf32_round(x3));
            } else {
                // hi/lo split store: q3 layout [hi|lo|hi], k3 layout [hi|hi|lo]
                float h0 = tf32_round(x0), h1 = tf32_round(x1);
                float h2 = tf32_round(x2), h3 = tf32_round(x3);
                float l0 = tf32_round(x0 - h0), l1 = tf32_round(x1 - h1);
                float l2 = tf32_round(x2 - h2), l3 = tf32_round(x3 - h3);
                int c_hi2 = (MODE == 1) ? c0 + 2 * RANK : c0 + RANK;
                int c_lo  = (MODE == 1) ? c0 + RANK     : c0 + 2 * RANK;
                *(float2*)(Cb + (size_t)r0 * ldc + c0)          = make_float2(h0, h1);
                *(float2*)(Cb + (size_t)(r0 + 8) * ldc + c0)    = make_float2(h2, h3);
                *(float2*)(Cb + (size_t)r0 * ldc + c_hi2)       = make_float2(h0, h1);
                *(float2*)(Cb + (size_t)(r0 + 8) * ldc + c_hi2) = make_float2(h2, h3);
                *(float2*)(Cb + (size_t)r0 * ldc + c_lo)        = make_float2(l0, l1);
                *(float2*)(Cb + (size_t)(r0 + 8) * ldc + c_lo)  = make_float2(l2, l3);
            }
        }
    }
}

// ---------------------------------------------------------------------------
// Row softmax, in place, rounds probs to tf32. One CTA per row of 2048.
// ---------------------------------------------------------------------------
__global__ void __launch_bounds__(256) softmax_kernel(float* __restrict__ S)
{
    float4* row = (float4*)(S + (size_t)blockIdx.x * SEQ);
    const int tid = threadIdx.x;

    float4 a = row[tid];
    float4 b = row[tid + 256];

    float m = fmaxf(fmaxf(fmaxf(a.x, a.y), fmaxf(a.z, a.w)),
                    fmaxf(fmaxf(b.x, b.y), fmaxf(b.z, b.w)));

    __shared__ float red[8];
#pragma unroll
    for (int o = 16; o; o >>= 1) m = fmaxf(m, __shfl_xor_sync(0xffffffffu, m, o));
    if ((tid & 31) == 0) red[tid >> 5] = m;
    __syncthreads();
    m = red[0];
#pragma unroll
    for (int i = 1; i < 8; i++) m = fmaxf(m, red[i]);
    __syncthreads();

    a.x = __expf(a.x - m); a.y = __expf(a.y - m);
    a.z = __expf(a.z - m); a.w = __expf(a.w - m);
    b.x = __expf(b.x - m); b.y = __expf(b.y - m);
    b.z = __expf(b.z - m); b.w = __expf(b.w - m);

    float s = a.x + a.y + a.z + a.w + b.x + b.y + b.z + b.w;
#pragma unroll
    for (int o = 16; o; o >>= 1) s += __shfl_xor_sync(0xffffffffu, s, o);
    if ((tid & 31) == 0) red[tid >> 5] = s;
    __syncthreads();
    float tot = red[0];
#pragma unroll
    for (int i = 1; i < 8; i++) tot += red[i];

    float inv = 1.0f / tot;
    a.x = tf32_round(a.x * inv); a.y = tf32_round(a.y * inv);
    a.z = tf32_round(a.z * inv); a.w = tf32_round(a.w * inv);
    b.x = tf32_round(b.x * inv); b.y = tf32_round(b.y * inv);
    b.z = tf32_round(b.z * inv); b.w = tf32_round(b.w * inv);

    row[tid]       = a;
    row[tid + 256] = b;
}

// ---------------------------------------------------------------------------
// launch
// ---------------------------------------------------------------------------
extern "C" void kernel_launch(void* const* d_in, const int* in_sizes, int n_in,
                              void* d_out, int out_size)
{
    (void)in_sizes; (void)n_in; (void)out_size;
    const float* x  = (const float*)d_in[0];
    const float* Wq = (const float*)d_in[1];
    const float* Wk = (const float*)d_in[2];
    const float* Wv = (const float*)d_in[3];
    float* out = (float*)d_out;

    void *pq, *pk, *pv, *ps;
    cudaGetSymbolAddress(&pq, g_q3);
    cudaGetSymbolAddress(&pk, g_k3);
    cudaGetSymbolAddress(&pv, g_vT);
    cudaGetSymbolAddress(&ps, g_s);
    float* q3 = (float*)pq;
    float* k3 = (float*)pk;
    float* vT = (float*)pv;
    float* s  = (float*)ps;

    const int SMEM = 2 * (2 * 128 * 36) * 4;   // 73728 B

    cudaFuncSetAttribute((const void*)gemm_kernel<true,  true,  1>,
                         cudaFuncAttributeMaxDynamicSharedMemorySize, SMEM);
    cudaFuncSetAttribute((const void*)gemm_kernel<true,  true,  2>,
                         cudaFuncAttributeMaxDynamicSharedMemorySize, SMEM);
    cudaFuncSetAttribute((const void*)gemm_kernel<true,  false, 3>,
                         cudaFuncAttributeMaxDynamicSharedMemorySize, SMEM);
    cudaFuncSetAttribute((const void*)gemm_kernel<false, false, 0>,
                         cudaFuncAttributeMaxDynamicSharedMemorySize, SMEM);

    const int MT = BATCH * SEQ;               // 16384 flattened tokens
    const int R3 = 3 * RANK;                  // 384
    const float scale = 0.08838834764831845f; // 1/sqrt(128)

    // K1: q3 = split(x @ Wq^T)   [MT, 384] layout [hi|lo|hi]
    gemm_kernel<true, true, 1><<<dim3(1, MT / BM, 1), NTHREADS, SMEM>>>(
        x, Wq, q3, MT, RANK, DIM, DIM, DIM, R3, 0, 0, 0, 1.f);
    // K2: k3 = split(x @ Wk^T)   [MT, 384] layout [hi|hi|lo]
    gemm_kernel<true, true, 2><<<dim3(1, MT / BM, 1), NTHREADS, SMEM>>>(
        x, Wk, k3, MT, RANK, DIM, DIM, DIM, R3, 0, 0, 0, 1.f);
    // K3: vT = round(Wv @ x^T)   [DIM, MT]
    gemm_kernel<true, false, 3><<<dim3(MT / BN, DIM / BM, 1), NTHREADS, SMEM>>>(
        Wv, x, vT, DIM, MT, DIM, DIM, DIM, MT, 0, 0, 0, 1.f);
    // K4: s = q3 @ k3^T * scale  (plain tf32 == 3x compensated, batched)
    gemm_kernel<false, false, 0><<<dim3(SEQ / BN, SEQ / BM, BATCH), NTHREADS, SMEM>>>(
        q3, k3, s, SEQ, SEQ, R3, R3, R3, SEQ,
        (long)SEQ * R3, (long)SEQ * R3, (long)SEQ * SEQ, scale);
    // K5: softmax rows (in place, rounds to tf32)
    softmax_kernel<<<BATCH * SEQ, 256>>>(s);
    // K6: out = probs @ v  ==  A=probs [S,S], B=vT rows (K-major), batched
    gemm_kernel<false, false, 0><<<dim3(DIM / BN, SEQ / BM, BATCH), NTHREADS, SMEM>>>(
        s, vT, out, SEQ, DIM, SEQ, SEQ, MT, DIM,
        (long)SEQ * SEQ, (long)SEQ, (long)SEQ * DIM, 1.f);
}

// round 5
// speedup vs baseline: 1.4654x; 1.3557x over previous
#include <cuda_runtime.h>
#include <cuda_fp16.h>
#include <cstdint>

// ---------------------------------------------------------------------------
// PrefilledAttention: B=8, S=2048, D=1024, R=128 — all-fp16 mma (m16n8k16)
// with hi/lo compensated splits:
//   P0:  x -> x3 = [xh|xl|xh]  (fp16, K=3072);  W -> W3 = [Wh|Wh|Wl]
//   K1:  q  = x3 @ Wq3^T  (== 3-term compensated == near-fp32), split->q3
//   K2:  k  = x3 @ Wk3^T  -> k3
//   K3:  vT = Wv3 @ x3^T  -> fp16 vT [D, B*S]
//   K4:  s  = q3 @ k3^T * 1/sqrt(128)   (K=384 fp16, 3-term logits)
//   K5:  softmax rows -> fp16 probs
//   K6:  out = probs @ v  (single fp16 pass, fp32 accum)
// ---------------------------------------------------------------------------

#define BATCH 8
#define SEQ   2048
#define DIM   1024
#define RANK  128

#define BM 128
#define BN 128
#define BK 64          // halfs
#define NTHREADS 256

// Scratch (allocation-free rule: __device__ globals)
__device__ __half g_x3 [(size_t)BATCH * SEQ * 3 * DIM];     // 100.7 MB
__device__ __half g_wq3[(size_t)RANK * 3 * DIM];
__device__ __half g_wk3[(size_t)RANK * 3 * DIM];
__device__ __half g_wv3[(size_t)DIM * 3 * DIM];
__device__ __half g_q3 [(size_t)BATCH * SEQ * 3 * RANK];    // 12.6 MB
__device__ __half g_k3 [(size_t)BATCH * SEQ * 3 * RANK];
__device__ __half g_vT [(size_t)DIM * BATCH * SEQ];         // 33.6 MB
__device__ float  g_s  [(size_t)BATCH * SEQ * SEQ];         // 128 MB
__device__ __half g_p  [(size_t)BATCH * SEQ * SEQ];         // 67 MB

// ---------------------------------------------------------------------------
__device__ __forceinline__ void cp_async16(void* smem, const void* gmem) {
    uint32_t s = (uint32_t)__cvta_generic_to_shared(smem);
    asm volatile("cp.async.cg.shared.global [%0], [%1], 16;\n" :: "r"(s), "l"(gmem));
}
__device__ __forceinline__ void cp_commit() {
    asm volatile("cp.async.commit_group;\n");
}
template <int N>
__device__ __forceinline__ void cp_wait() {
    asm volatile("cp.async.wait_group %0;\n" :: "n"(N));
}

__device__ __forceinline__ void ldsm4(uint32_t& d0, uint32_t& d1,
                                      uint32_t& d2, uint32_t& d3, uint32_t addr) {
    asm volatile("ldmatrix.sync.aligned.m8n8.x4.shared.b16 {%0,%1,%2,%3}, [%4];"
                 : "=r"(d0), "=r"(d1), "=r"(d2), "=r"(d3) : "r"(addr));
}

__device__ __forceinline__ void mma_f16(float* c, const uint32_t* a, const uint32_t* b) {
    asm volatile(
        "mma.sync.aligned.m16n8k16.row.col.f32.f16.f16.f32 "
        "{%0,%1,%2,%3}, {%4,%5,%6,%7}, {%8,%9}, {%0,%1,%2,%3};"
        : "+f"(c[0]), "+f"(c[1]), "+f"(c[2]), "+f"(c[3])
        : "r"(a[0]), "r"(a[1]), "r"(a[2]), "r"(a[3]), "r"(b[0]), "r"(b[1]));
}

// ---------------------------------------------------------------------------
// fp16 tiled GEMM:  C[M,N] = alpha * A[M,K] * B^T   (A,B fp16 K-contiguous)
//   MODE 0: fp32 store     MODE 1: q-split [qh|ql|qh] (ldc=384)
//   MODE 2: k-split [kh|kh|kl]                 MODE 3: fp16-rounded store
// ---------------------------------------------------------------------------
template <int MODE>
__global__ void __launch_bounds__(NTHREADS, 2)
gemm16_kernel(const __half* __restrict__ A, const __half* __restrict__ Bm,
              void* __restrict__ C, int K,
              int lda, int ldb, int ldc,
              long aS, long bS, long cS, float alpha)
{
    constexpr int ST    = 72;                // padded smem stride (halfs)
    constexpr int TSZ   = 128 * ST;          // one 128x64 tile (halfs)
    constexpr int STAGE = 2 * TSZ;           // A + B tile (halfs)
    constexpr int STAGE_B = STAGE * 2;       // bytes

    extern __shared__ __half smh[];

    const __half* Ab = A  + (long)blockIdx.z * aS;
    const __half* Bb = Bm + (long)blockIdx.z * bS;

    const int bm = blockIdx.y * BM;
    const int bn = blockIdx.x * BN;
    const int tid = threadIdx.x;

    const int row = tid >> 3;             // 0..31
    const int c8  = (tid & 7) * 8;        // half offset, 16B granularity

    auto load_tile = [&](int kt, int stage) {
        __half* As = smh + stage * STAGE;
        __half* Bs = As + TSZ;
        const __half* Ag = Ab + (size_t)bm * lda + kt * BK;
        const __half* Bg = Bb + (size_t)bn * ldb + kt * BK;
#pragma unroll
        for (int i = 0; i < 4; i++) {
            int r = row + i * 32;
            cp_async16(&As[r * ST + c8], Ag + (size_t)r * lda + c8);
            cp_async16(&Bs[r * ST + c8], Bg + (size_t)r * ldb + c8);
        }
    };

    // warp/fragment indexing
    const int lane = tid & 31;
    const int warp = tid >> 5;
    const int wm = warp & 1;          // 2 warps along M (64 rows each)
    const int wn = warp >> 1;         // 4 warps along N (32 cols each)
    const int g  = lane >> 2;         // 0..7
    const int tg = lane & 3;          // 0..3

    // ldmatrix per-lane byte offsets within a stage
    const uint32_t sbase = (uint32_t)__cvta_generic_to_shared(smh);
    const uint32_t a_off = ((wm * 64 + (lane & 7) + ((lane >> 3) & 1) * 8) * ST
                            + ((lane >> 4) & 1) * 8) * 2;
    const uint32_t b_off = ((wn * 32 + ((lane >> 4) & 1) * 8 + (lane & 7)) * ST
                            + ((lane >> 3) & 1) * 8) * 2 + TSZ * 2;

    float acc[4][4][4];
#pragma unroll
    for (int a = 0; a < 4; a++)
#pragma unroll
        for (int b = 0; b < 4; b++)
#pragma unroll
            for (int c = 0; c < 4; c++) acc[a][b][c] = 0.f;

    const int KT = K / BK;
    load_tile(0, 0);
    cp_commit();

    for (int kt = 0; kt < KT; kt++) {
        if (kt + 1 < KT) {
            load_tile(kt + 1, (kt + 1) & 1);
            cp_commit();
            cp_wait<1>();
        } else {
            cp_wait<0>();
        }
        __syncthreads();

        const uint32_t stg = sbase + (kt & 1) * STAGE_B;
        const uint32_t aA = stg + a_off;
        const uint32_t aB = stg + b_off;

#pragma unroll
        for (int ks = 0; ks < 4; ks++) {          // 4 k-slices of 16
            const uint32_t ksb = ks * 32;         // 16 halfs

            uint32_t af[4][4];
#pragma unroll
            for (int mf = 0; mf < 4; mf++)
                ldsm4(af[mf][0], af[mf][1], af[mf][2], af[mf][3],
                      aA + mf * (16 * ST * 2) + ksb);

            uint32_t bf[4][2];
            ldsm4(bf[0][0], bf[0][1], bf[1][0], bf[1][1], aB + ksb);
            ldsm4(bf[2][0], bf[2][1], bf[3][0], bf[3][1],
                  aB + (16 * ST * 2) + ksb);

#pragma unroll
            for (int mf = 0; mf < 4; mf++)
#pragma unroll
                for (int nf = 0; nf < 4; nf++)
                    mma_f16(acc[mf][nf], af[mf], bf[nf]);
        }
        __syncthreads();
    }

    // ---- epilogue ----
#pragma unroll
    for (int mf = 0; mf < 4; mf++) {
        int r0 = bm + wm * 64 + mf * 16 + g;
#pragma unroll
        for (int nf = 0; nf < 4; nf++) {
            int c0 = bn + wn * 32 + nf * 8 + tg * 2;
            float x0 = acc[mf][nf][0] * alpha;
            float x1 = acc[mf][nf][1] * alpha;
            float x2 = acc[mf][nf][2] * alpha;
            float x3 = acc[mf][nf][3] * alpha;
            if (MODE == 0) {
                float* Cf = (float*)C + (long)blockIdx.z * cS;
                *(float2*)(Cf + (size_t)r0 * ldc + c0)       = make_float2(x0, x1);
                *(float2*)(Cf + (size_t)(r0 + 8) * ldc + c0) = make_float2(x2, x3);
            } else if (MODE == 3) {
                __half* Ch = (__half*)C + (long)blockIdx.z * cS;
                *(__half2*)(Ch + (size_t)r0 * ldc + c0) = __floats2half2_rn(x0, x1);
                *(__half2*)(Ch + (size_t)(r0 + 8) * ldc + c0) = __floats2half2_rn(x2, x3);
            } else {
                // hi/lo split: MODE 1 -> [h|l|h], MODE 2 -> [h|h|l]
                __half* Ch = (__half*)C + (long)blockIdx.z * cS;
                __half h0 = __float2half_rn(x0), h1 = __float2half_rn(x1);
                __half h2 = __float2half_rn(x2), h3 = __float2half_rn(x3);
                __half l0 = __float2half_rn(x0 - __half2float(h0));
                __half l1 = __float2half_rn(x1 - __half2float(h1));
                __half l2 = __float2half_rn(x2 - __half2float(h2));
                __half l3 = __float2half_rn(x3 - __half2float(h3));
                __half2 hi01 = __halves2half2(h0, h1), hi23 = __halves2half2(h2, h3);
                __half2 lo01 = __halves2half2(l0, l1), lo23 = __halves2half2(l2, l3);
                int c_mid = c0 + RANK, c_end = c0 + 2 * RANK;
                __half2 m01 = (MODE == 1) ? lo01 : hi01;
                __half2 m23 = (MODE == 1) ? lo23 : hi23;
                __half2 e01 = (MODE == 1) ? hi01 : lo01;
                __half2 e23 = (MODE == 1) ? hi23 : lo23;
                *(__half2*)(Ch + (size_t)r0 * ldc + c0)          = hi01;
                *(__half2*)(Ch + (size_t)(r0 + 8) * ldc + c0)    = hi23;
                *(__half2*)(Ch + (size_t)r0 * ldc + c_mid)       = m01;
                *(__half2*)(Ch + (size_t)(r0 + 8) * ldc + c_mid) = m23;
                *(__half2*)(Ch + (size_t)r0 * ldc + c_end)       = e01;
                *(__half2*)(Ch + (size_t)(r0 + 8) * ldc + c_end) = e23;
            }
        }
    }
}

// ---------------------------------------------------------------------------
// P0: hi/lo split.  LHL=1: [h|l|h] (for x);  LHL=0: [h|h|l] (for W)
// Input  [rows, 1024] fp32 -> output [rows, 3072] fp16.
// One block per row-quarter: idx -> (row, 4 cols).
// ---------------------------------------------------------------------------
template <int LHL>
__global__ void __launch_bounds__(256) split_kernel(
    const float* __restrict__ in, __half* __restrict__ out)
{
    size_t idx = (size_t)blockIdx.x * 256 + threadIdx.x;  // (rows*256)
    size_t m = idx >> 8;
    int d = (int)(idx & 255) * 4;
    float4 v = *(const float4*)(in + m * DIM + d);

    __half h0 = __float2half_rn(v.x), h1 = __float2half_rn(v.y);
    __half h2 = __float2half_rn(v.z), h3 = __float2half_rn(v.w);
    __half l0 = __float2half_rn(v.x - __half2float(h0));
    __half l1 = __float2half_rn(v.y - __half2float(h1));
    __half l2 = __float2half_rn(v.z - __half2float(h2));
    __half l3 = __float2half_rn(v.w - __half2float(h3));

    __half* o = out + m * (3 * DIM);
    __half2 hi01 = __halves2half2(h0, h1), hi23 = __halves2half2(h2, h3);
    __half2 lo01 = __halves2half2(l0, l1), lo23 = __halves2half2(l2, l3);

    *(__half2*)(o + d)     = hi01;
    *(__half2*)(o + d + 2) = hi23;
    if (LHL) {   // [h|l|h]
        *(__half2*)(o + DIM + d)         = lo01;
        *(__half2*)(o + DIM + d + 2)     = lo23;
        *(__half2*)(o + 2 * DIM + d)     = hi01;
        *(__half2*)(o + 2 * DIM + d + 2) = hi23;
    } else {     // [h|h|l]
        *(__half2*)(o + DIM + d)         = hi01;
        *(__half2*)(o + DIM + d + 2)     = hi23;
        *(__half2*)(o + 2 * DIM + d)     = lo01;
        *(__half2*)(o + 2 * DIM + d + 2) = lo23;
    }
}

// ---------------------------------------------------------------------------
// Row softmax: fp32 scores in, fp16 probs out. One CTA per row of 2048.
// ---------------------------------------------------------------------------
__global__ void __launch_bounds__(256) softmax_kernel(
    const float* __restrict__ S, __half* __restrict__ P)
{
    const float4* row = (const float4*)(S + (size_t)blockIdx.x * SEQ);
    __half* prow = P + (size_t)blockIdx.x * SEQ;
    const int tid = threadIdx.x;

    float4 a = row[tid];
    float4 b = row[tid + 256];

    float m = fmaxf(fmaxf(fmaxf(a.x, a.y), fmaxf(a.z, a.w)),
                    fmaxf(fmaxf(b.x, b.y), fmaxf(b.z, b.w)));

    __shared__ float red[8];
#pragma unroll
    for (int o = 16; o; o >>= 1) m = fmaxf(m, __shfl_xor_sync(0xffffffffu, m, o));
    if ((tid & 31) == 0) red[tid >> 5] = m;
    __syncthreads();
    m = red[0];
#pragma unroll
    for (int i = 1; i < 8; i++) m = fmaxf(m, red[i]);
    __syncthreads();

    a.x = __expf(a.x - m); a.y = __expf(a.y - m);
    a.z = __expf(a.z - m); a.w = __expf(a.w - m);
    b.x = __expf(b.x - m); b.y = __expf(b.y - m);
    b.z = __expf(b.z - m); b.w = __expf(b.w - m);

    float s = a.x + a.y + a.z + a.w + b.x + b.y + b.z + b.w;
#pragma unroll
    for (int o = 16; o; o >>= 1) s += __shfl_xor_sync(0xffffffffu, s, o);
    if ((tid & 31) == 0) red[tid >> 5] = s;
    __syncthreads();
    float tot = red[0];
#pragma unroll
    for (int i = 1; i < 8; i++) tot += red[i];

    float inv = 1.0f / tot;
    __half2 p0 = __floats2half2_rn(a.x * inv, a.y * inv);
    __half2 p1 = __floats2half2_rn(a.z * inv, a.w * inv);
    __half2 p2 = __floats2half2_rn(b.x * inv, b.y * inv);
    __half2 p3 = __floats2half2_rn(b.z * inv, b.w * inv);

    *(__half2*)(prow + tid * 4)              = p0;
    *(__half2*)(prow + tid * 4 + 2)          = p1;
    *(__half2*)(prow + 1024 + tid * 4)       = p2;
    *(__half2*)(prow + 1024 + tid * 4 + 2)   = p3;
}

// ---------------------------------------------------------------------------
// launch
// ---------------------------------------------------------------------------
extern "C" void kernel_launch(void* const* d_in, const int* in_sizes, int n_in,
                              void* d_out, int out_size)
{
    (void)in_sizes; (void)n_in; (void)out_size;
    const float* x  = (const float*)d_in[0];
    const float* Wq = (const float*)d_in[1];
    const float* Wk = (const float*)d_in[2];
    const float* Wv = (const float*)d_in[3];
    float* out = (float*)d_out;

    void *px3, *pwq, *pwk, *pwv, *pq, *pk, *pv, *ps, *pp;
    cudaGetSymbolAddress(&px3, g_x3);
    cudaGetSymbolAddress(&pwq, g_wq3);
    cudaGetSymbolAddress(&pwk, g_wk3);
    cudaGetSymbolAddress(&pwv, g_wv3);
    cudaGetSymbolAddress(&pq,  g_q3);
    cudaGetSymbolAddress(&pk,  g_k3);
    cudaGetSymbolAddress(&pv,  g_vT);
    cudaGetSymbolAddress(&ps,  g_s);
    cudaGetSymbolAddress(&pp,  g_p);
    __half* x3  = (__half*)px3;
    __half* wq3 = (__half*)pwq;
    __half* wk3 = (__half*)pwk;
    __half* wv3 = (__half*)pwv;
    __half* q3  = (__half*)pq;
    __half* k3  = (__half*)pk;
    __half* vT  = (__half*)pv;
    float*  s   = (float*)ps;
    __half* p   = (__half*)pp;

    const int SMEM = 2 * (2 * 128 * 72) * 2;   // 73728 B

    cudaFuncSetAttribute((const void*)gemm16_kernel<0>,
                         cudaFuncAttributeMaxDynamicSharedMemorySize, SMEM);
    cudaFuncSetAttribute((const void*)gemm16_kernel<1>,
                         cudaFuncAttributeMaxDynamicSharedMemorySize, SMEM);
    cudaFuncSetAttribute((const void*)gemm16_kernel<2>,
                         cudaFuncAttributeMaxDynamicSharedMemorySize, SMEM);
    cudaFuncSetAttribute((const void*)gemm16_kernel<3>,
                         cudaFuncAttributeMaxDynamicSharedMemorySize, SMEM);

    const int MT = BATCH * SEQ;               // 16384
    const int K3X = 3 * DIM;                  // 3072
    const int R3 = 3 * RANK;                  // 384
    const float scale = 0.08838834764831845f; // 1/sqrt(128)

    // P0: splits
    split_kernel<1><<<MT, 256>>>(x, x3);              // x3 = [xh|xl|xh]
    split_kernel<0><<<RANK, 256>>>(Wq, wq3);          // [Wh|Wh|Wl]
    split_kernel<0><<<RANK, 256>>>(Wk, wk3);
    split_kernel<0><<<DIM, 256>>>(Wv, wv3);

    // K1: q3 = split(x3 @ wq3^T)  [MT, 384] = [qh|ql|qh]
    gemm16_kernel<1><<<dim3(1, MT / BM, 1), NTHREADS, SMEM>>>(
        x3, wq3, q3, K3X, K3X, K3X, R3, 0, 0, 0, 1.f);
    // K2: k3 = split(x3 @ wk3^T)  [MT, 384] = [kh|kh|kl]
    gemm16_kernel<2><<<dim3(1, MT / BM, 1), NTHREADS, SMEM>>>(
        x3, wk3, k3, K3X, K3X, K3X, R3, 0, 0, 0, 1.f);
    // K3: vT = fp16(wv3 @ x3^T)   [DIM, MT]
    gemm16_kernel<3><<<dim3(MT / BN, DIM / BM, 1), NTHREADS, SMEM>>>(
        wv3, x3, vT, K3X, K3X, K3X, MT, 0, 0, 0, 1.f);
    // K4: s = q3 @ k3^T * scale   (fp32 out, batched)
    gemm16_kernel<0><<<dim3(SEQ / BN, SEQ / BM, BATCH), NTHREADS, SMEM>>>(
        q3, k3, s, R3, R3, R3, SEQ,
        (long)SEQ * R3, (long)SEQ * R3, (long)SEQ * SEQ, scale);
    // K5: softmax rows -> fp16 probs
    softmax_kernel<<<BATCH * SEQ, 256>>>(s, p);
    // K6: out = p @ v  (A=p [S,S] fp16, B=vT rows K-major, batched)
    gemm16_kernel<0><<<dim3(DIM / BN, SEQ / BM, BATCH), NTHREADS, SMEM>>>(
        p, vT, out, SEQ, SEQ, MT, DIM,
        (long)SEQ * SEQ, (long)SEQ, (long)SEQ * DIM, 1.f);
}

// round 7
// speedup vs baseline: 1.9521x; 1.3321x over previous
#include <cuda_runtime.h>
#include <cuda_fp16.h>
#include <cstdint>

// ---------------------------------------------------------------------------
// PrefilledAttention: B=8, S=2048, D=1024, R=128 — all-fp16 mma (m16n8k16)
//   P0:  x -> x3 = [xh|xl|xh]  (fp16, K=3072);  W -> W3 = [Wh|Wh|Wl]
//   K1:  q  = x3 @ Wq3^T  (3-term compensated, K=3072) -> q3 [qh|ql|qh]
//   K2:  k  = x3 @ Wk3^T  -> k3 [kh|kh|kl]
//   K3:  vT = xh @ Wvh^T  (1-pass fp16, K=1024 — v path tolerates ~2.4e-4)
//   K4:  s  = q3 @ k3^T * 1/sqrt(128)   (K=384, fp16 logit store)
//   K5:  softmax rows (fp16 in) -> fp16 probs
//   K6:  out = probs @ v  (fp16, fp32 accum + store)
// ---------------------------------------------------------------------------

#define BATCH 8
#define SEQ   2048
#define DIM   1024
#define RANK  128

#define BM 128
#define BN 128
#define BK 64          // halfs
#define NTHREADS 256

// Scratch (allocation-free rule: __device__ globals)
__device__ __half g_x3 [(size_t)BATCH * SEQ * 3 * DIM];     // 100.7 MB
__device__ __half g_wq3[(size_t)RANK * 3 * DIM];
__device__ __half g_wk3[(size_t)RANK * 3 * DIM];
__device__ __half g_wv3[(size_t)DIM * 3 * DIM];
__device__ __half g_q3 [(size_t)BATCH * SEQ * 3 * RANK];    // 12.6 MB
__device__ __half g_k3 [(size_t)BATCH * SEQ * 3 * RANK];
__device__ __half g_vT [(size_t)DIM * BATCH * SEQ];         // 33.6 MB
__device__ __half g_s  [(size_t)BATCH * SEQ * SEQ];         // 67 MB (fp16 logits)
__device__ __half g_p  [(size_t)BATCH * SEQ * SEQ];         // 67 MB

// ---------------------------------------------------------------------------
__device__ __forceinline__ void cp_async16(void* smem, const void* gmem) {
    uint32_t s = (uint32_t)__cvta_generic_to_shared(smem);
    asm volatile("cp.async.cg.shared.global [%0], [%1], 16;\n" :: "r"(s), "l"(gmem));
}
__device__ __forceinline__ void cp_commit() {
    asm volatile("cp.async.commit_group;\n");
}
template <int N>
__device__ __forceinline__ void cp_wait() {
    asm volatile("cp.async.wait_group %0;\n" :: "n"(N));
}

__device__ __forceinline__ void ldsm4(uint32_t& d0, uint32_t& d1,
                                      uint32_t& d2, uint32_t& d3, uint32_t addr) {
    asm volatile("ldmatrix.sync.aligned.m8n8.x4.shared.b16 {%0,%1,%2,%3}, [%4];"
                 : "=r"(d0), "=r"(d1), "=r"(d2), "=r"(d3) : "r"(addr));
}

__device__ __forceinline__ void mma_f16(float* c, const uint32_t* a, const uint32_t* b) {
    asm volatile(
        "mma.sync.aligned.m16n8k16.row.col.f32.f16.f16.f32 "
        "{%0,%1,%2,%3}, {%4,%5,%6,%7}, {%8,%9}, {%0,%1,%2,%3};"
        : "+f"(c[0]), "+f"(c[1]), "+f"(c[2]), "+f"(c[3])
        : "r"(a[0]), "r"(a[1]), "r"(a[2]), "r"(a[3]), "r"(b[0]), "r"(b[1]));
}

// ---------------------------------------------------------------------------
// fp16 tiled GEMM:  C[M,N] = alpha * A[M,K] * B^T   (A,B fp16 K-contiguous)
//   MODE 0: fp32 store     MODE 1: q-split [qh|ql|qh] (ldc=384)
//   MODE 2: k-split [kh|kh|kl]                 MODE 3: fp16-rounded store
// ---------------------------------------------------------------------------
template <int MODE>
__global__ void __launch_bounds__(NTHREADS, 2)
gemm16_kernel(const __half* __restrict__ A, const __half* __restrict__ Bm,
              void* __restrict__ C, int K,
              int lda, int ldb, int ldc,
              long aS, long bS, long cS, float alpha)
{
    constexpr int ST    = 72;                // padded smem stride (halfs)
    constexpr int TSZ   = 128 * ST;          // one 128x64 tile (halfs)
    constexpr int STAGE = 2 * TSZ;           // A + B tile (halfs)
    constexpr int STAGE_B = STAGE * 2;       // bytes

    extern __shared__ __half smh[];

    const __half* Ab = A  + (long)blockIdx.z * aS;
    const __half* Bb = Bm + (long)blockIdx.z * bS;

    const int bm = blockIdx.y * BM;
    const int bn = blockIdx.x * BN;
    const int tid = threadIdx.x;

    const int row = tid >> 3;             // 0..31
    const int c8  = (tid & 7) * 8;        // half offset, 16B granularity

    auto load_tile = [&](int kt, int stage) {
        __half* As = smh + stage * STAGE;
        __half* Bs = As + TSZ;
        const __half* Ag = Ab + (size_t)bm * lda + kt * BK;
        const __half* Bg = Bb + (size_t)bn * ldb + kt * BK;
#pragma unroll
        for (int i = 0; i < 4; i++) {
            int r = row + i * 32;
            cp_async16(&As[r * ST + c8], Ag + (size_t)r * lda + c8);
            cp_async16(&Bs[r * ST + c8], Bg + (size_t)r * ldb + c8);
        }
    };

    // warp/fragment indexing
    const int lane = tid & 31;
    const int warp = tid >> 5;
    const int wm = warp & 1;          // 2 warps along M (64 rows each)
    const int wn = warp >> 1;         // 4 warps along N (32 cols each)
    const int g  = lane >> 2;         // 0..7
    const int tg = lane & 3;          // 0..3

    // ldmatrix per-lane byte offsets within a stage
    const uint32_t sbase = (uint32_t)__cvta_generic_to_shared(smh);
    const uint32_t a_off = ((wm * 64 + (lane & 7) + ((lane >> 3) & 1) * 8) * ST
                            + ((lane >> 4) & 1) * 8) * 2;
    const uint32_t b_off = ((wn * 32 + ((lane >> 4) & 1) * 8 + (lane & 7)) * ST
                            + ((lane >> 3) & 1) * 8) * 2 + TSZ * 2;

    float acc[4][4][4];
#pragma unroll
    for (int a = 0; a < 4; a++)
#pragma unroll
        for (int b = 0; b < 4; b++)
#pragma unroll
            for (int c = 0; c < 4; c++) acc[a][b][c] = 0.f;

    const int KT = K / BK;
    load_tile(0, 0);
    cp_commit();

    for (int kt = 0; kt < KT; kt++) {
        if (kt + 1 < KT) {
            load_tile(kt + 1, (kt + 1) & 1);
            cp_commit();
            cp_wait<1>();
        } else {
            cp_wait<0>();
        }
        __syncthreads();

        const uint32_t stg = sbase + (kt & 1) * STAGE_B;
        const uint32_t aA = stg + a_off;
        const uint32_t aB = stg + b_off;

#pragma unroll
        for (int ks = 0; ks < 4; ks++) {          // 4 k-slices of 16
            const uint32_t ksb = ks * 32;         // 16 halfs

            uint32_t af[4][4];
#pragma unroll
            for (int mf = 0; mf < 4; mf++)
                ldsm4(af[mf][0], af[mf][1], af[mf][2], af[mf][3],
                      aA + mf * (16 * ST * 2) + ksb);

            uint32_t bf[4][2];
            ldsm4(bf[0][0], bf[0][1], bf[1][0], bf[1][1], aB + ksb);
            ldsm4(bf[2][0], bf[2][1], bf[3][0], bf[3][1],
                  aB + (16 * ST * 2) + ksb);

#pragma unroll
            for (int mf = 0; mf < 4; mf++)
#pragma unroll
                for (int nf = 0; nf < 4; nf++)
                    mma_f16(acc[mf][nf], af[mf], bf[nf]);
        }
        __syncthreads();
    }

    // ---- epilogue ----
#pragma unroll
    for (int mf = 0; mf < 4; mf++) {
        int r0 = bm + wm * 64 + mf * 16 + g;
#pragma unroll
        for (int nf = 0; nf < 4; nf++) {
            int c0 = bn + wn * 32 + nf * 8 + tg * 2;
            float x0 = acc[mf][nf][0] * alpha;
            float x1 = acc[mf][nf][1] * alpha;
            float x2 = acc[mf][nf][2] * alpha;
            float x3 = acc[mf][nf][3] * alpha;
            if (MODE == 0) {
                float* Cf = (float*)C + (long)blockIdx.z * cS;
                *(float2*)(Cf + (size_t)r0 * ldc + c0)       = make_float2(x0, x1);
                *(float2*)(Cf + (size_t)(r0 + 8) * ldc + c0) = make_float2(x2, x3);
            } else if (MODE == 3) {
                __half* Ch = (__half*)C + (long)blockIdx.z * cS;
                *(__half2*)(Ch + (size_t)r0 * ldc + c0) = __floats2half2_rn(x0, x1);
                *(__half2*)(Ch + (size_t)(r0 + 8) * ldc + c0) = __floats2half2_rn(x2, x3);
            } else {
                // hi/lo split: MODE 1 -> [h|l|h], MODE 2 -> [h|h|l]
                __half* Ch = (__half*)C + (long)blockIdx.z * cS;
                __half h0 = __float2half_rn(x0), h1 = __float2half_rn(x1);
                __half h2 = __float2half_rn(x2), h3 = __float2half_rn(x3);
                __half l0 = __float2half_rn(x0 - __half2float(h0));
                __half l1 = __float2half_rn(x1 - __half2float(h1));
                __half l2 = __float2half_rn(x2 - __half2float(h2));
                __half l3 = __float2half_rn(x3 - __half2float(h3));
                __half2 hi01 = __halves2half2(h0, h1), hi23 = __halves2half2(h2, h3);
                __half2 lo01 = __halves2half2(l0, l1), lo23 = __halves2half2(l2, l3);
                int c_mid = c0 + RANK, c_end = c0 + 2 * RANK;
                __half2 m01 = (MODE == 1) ? lo01 : hi01;
                __half2 m23 = (MODE == 1) ? lo23 : hi23;
                __half2 e01 = (MODE == 1) ? hi01 : lo01;
                __half2 e23 = (MODE == 1) ? hi23 : lo23;
                *(__half2*)(Ch + (size_t)r0 * ldc + c0)          = hi01;
                *(__half2*)(Ch + (size_t)(r0 + 8) * ldc + c0)    = hi23;
                *(__half2*)(Ch + (size_t)r0 * ldc + c_mid)       = m01;
                *(__half2*)(Ch + (size_t)(r0 + 8) * ldc + c_mid) = m23;
                *(__half2*)(Ch + (size_t)r0 * ldc + c_end)       = e01;
                *(__half2*)(Ch + (size_t)(r0 + 8) * ldc + c_end) = e23;
            }
        }
    }
}

// ---------------------------------------------------------------------------
// P0: hi/lo split.  LHL=1: [h|l|h] (for x);  LHL=0: [h|h|l] (for W)
// ---------------------------------------------------------------------------
template <int LHL>
__global__ void __launch_bounds__(256) split_kernel(
    const float* __restrict__ in, __half* __restrict__ out)
{
    size_t idx = (size_t)blockIdx.x * 256 + threadIdx.x;
    size_t m = idx >> 8;
    int d = (int)(idx & 255) * 4;
    float4 v = *(const float4*)(in + m * DIM + d);

    __half h0 = __float2half_rn(v.x), h1 = __float2half_rn(v.y);
    __half h2 = __float2half_rn(v.z), h3 = __float2half_rn(v.w);
    __half l0 = __float2half_rn(v.x - __half2float(h0));
    __half l1 = __float2half_rn(v.y - __half2float(h1));
    __half l2 = __float2half_rn(v.z - __half2float(h2));
    __half l3 = __float2half_rn(v.w - __half2float(h3));

    __half* o = out + m * (3 * DIM);
    __half2 hi01 = __halves2half2(h0, h1), hi23 = __halves2half2(h2, h3);
    __half2 lo01 = __halves2half2(l0, l1), lo23 = __halves2half2(l2, l3);

    *(__half2*)(o + d)     = hi01;
    *(__half2*)(o + d + 2) = hi23;
    if (LHL) {   // [h|l|h]
        *(__half2*)(o + DIM + d)         = lo01;
        *(__half2*)(o + DIM + d + 2)     = lo23;
        *(__half2*)(o + 2 * DIM + d)     = hi01;
        *(__half2*)(o + 2 * DIM + d + 2) = hi23;
    } else {     // [h|h|l]
        *(__half2*)(o + DIM + d)         = hi01;
        *(__half2*)(o + DIM + d + 2)     = hi23;
        *(__half2*)(o + 2 * DIM + d)     = lo01;
        *(__half2*)(o + 2 * DIM + d + 2) = lo23;
    }
}

// ---------------------------------------------------------------------------
// Row softmax: fp16 logits in, fp16 probs out. One CTA per row of 2048.
// Each thread owns 8 contiguous values (one uint4 = 8 halfs).
// ---------------------------------------------------------------------------
__global__ void __launch_bounds__(256) softmax_kernel(
    const __half* __restrict__ S, __half* __restrict__ P)
{
    const int tid = threadIdx.x;
    const uint4* row = (const uint4*)(S + (size_t)blockIdx.x * SEQ);
    uint4* prow = (uint4*)(P + (size_t)blockIdx.x * SEQ);

    uint4 pk = row[tid];
    __half2 h[4] = {*(__half2*)&pk.x, *(__half2*)&pk.y,
                    *(__half2*)&pk.z, *(__half2*)&pk.w};
    float v[8];
#pragma unroll
    for (int i = 0; i < 4; i++) {
        float2 f = __half22float2(h[i]);
        v[2 * i] = f.x; v[2 * i + 1] = f.y;
    }

    float m = v[0];
#pragma unroll
    for (int i = 1; i < 8; i++) m = fmaxf(m, v[i]);

    __shared__ float red[8];
#pragma unroll
    for (int o = 16; o; o >>= 1) m = fmaxf(m, __shfl_xor_sync(0xffffffffu, m, o));
    if ((tid & 31) == 0) red[tid >> 5] = m;
    __syncthreads();
    m = red[0];
#pragma unroll
    for (int i = 1; i < 8; i++) m = fmaxf(m, red[i]);
    __syncthreads();

    float s = 0.f;
#pragma unroll
    for (int i = 0; i < 8; i++) { v[i] = __expf(v[i] - m); s += v[i]; }

#pragma unroll
    for (int o = 16; o; o >>= 1) s += __shfl_xor_sync(0xffffffffu, s, o);
    if ((tid & 31) == 0) red[tid >> 5] = s;
    __syncthreads();
    float tot = red[0];
#pragma unroll
    for (int i = 1; i < 8; i++) tot += red[i];

    float inv = 1.0f / tot;
    uint4 po;
    __half2* ph = (__half2*)&po;
#pragma unroll
    for (int i = 0; i < 4; i++)
        ph[i] = __floats2half2_rn(v[2 * i] * inv, v[2 * i + 1] * inv);
    prow[tid] = po;
}

// ---------------------------------------------------------------------------
// launch
// ---------------------------------------------------------------------------
extern "C" void kernel_launch(void* const* d_in, const int* in_sizes, int n_in,
                              void* d_out, int out_size)
{
    (void)in_sizes; (void)n_in; (void)out_size;
    const float* x  = (const float*)d_in[0];
    const float* Wq = (const float*)d_in[1];
    const float* Wk = (const float*)d_in[2];
    const float* Wv = (const float*)d_in[3];
    float* out = (float*)d_out;

    void *px3, *pwq, *pwk, *pwv, *pq, *pk, *pv, *ps, *pp;
    cudaGetSymbolAddress(&px3, g_x3);
    cudaGetSymbolAddress(&pwq, g_wq3);
    cudaGetSymbolAddress(&pwk, g_wk3);
    cudaGetSymbolAddress(&pwv, g_wv3);
    cudaGetSymbolAddress(&pq,  g_q3);
    cudaGetSymbolAddress(&pk,  g_k3);
    cudaGetSymbolAddress(&pv,  g_vT);
    cudaGetSymbolAddress(&ps,  g_s);
    cudaGetSymbolAddress(&pp,  g_p);
    __half* x3  = (__half*)px3;
    __half* wq3 = (__half*)pwq;
    __half* wk3 = (__half*)pwk;
    __half* wv3 = (__half*)pwv;
    __half* q3  = (__half*)pq;
    __half* k3  = (__half*)pk;
    __half* vT  = (__half*)pv;
    __half* s   = (__half*)ps;
    __half* p   = (__half*)pp;

    const int SMEM = 2 * (2 * 128 * 72) * 2;   // 73728 B

    cudaFuncSetAttribute((const void*)gemm16_kernel<0>,
                         cudaFuncAttributeMaxDynamicSharedMemorySize, SMEM);
    cudaFuncSetAttribute((const void*)gemm16_kernel<1>,
                         cudaFuncAttributeMaxDynamicSharedMemorySize, SMEM);
    cudaFuncSetAttribute((const void*)gemm16_kernel<2>,
                         cudaFuncAttributeMaxDynamicSharedMemorySize, SMEM);
    cudaFuncSetAttribute((const void*)gemm16_kernel<3>,
                         cudaFuncAttributeMaxDynamicSharedMemorySize, SMEM);

    const int MT = BATCH * SEQ;               // 16384
    const int K3X = 3 * DIM;                  // 3072
    const int R3 = 3 * RANK;                  // 384
    const float scale = 0.08838834764831845f; // 1/sqrt(128)

    // P0: splits
    split_kernel<1><<<MT, 256>>>(x, x3);              // x3 = [xh|xl|xh]
    split_kernel<0><<<RANK, 256>>>(Wq, wq3);          // [Wh|Wh|Wl]
    split_kernel<0><<<RANK, 256>>>(Wk, wk3);
    split_kernel<0><<<DIM, 256>>>(Wv, wv3);

    // K1: q3 = split(x3 @ wq3^T)  [MT, 384] = [qh|ql|qh]  (3-term, K=3072)
    gemm16_kernel<1><<<dim3(1, MT / BM, 1), NTHREADS, SMEM>>>(
        x3, wq3, q3, K3X, K3X, K3X, R3, 0, 0, 0, 1.f);
    // K2: k3 = split(x3 @ wk3^T)  [MT, 384] = [kh|kh|kl]
    gemm16_kernel<2><<<dim3(1, MT / BM, 1), NTHREADS, SMEM>>>(
        x3, wk3, k3, K3X, K3X, K3X, R3, 0, 0, 0, 1.f);
    // K3: vT = fp16(xh @ Wvh^T)^T  -> 1-pass: A=Wvh (lda=3072), B=xh (ldb=3072)
    gemm16_kernel<3><<<dim3(MT / BN, DIM / BM, 1), NTHREADS, SMEM>>>(
        wv3, x3, vT, DIM, K3X, K3X, MT, 0, 0, 0, 1.f);
    // K4: s = fp16(q3 @ k3^T * scale)   (batched, fp16 logits)
    gemm16_kernel<3><<<dim3(SEQ / BN, SEQ / BM, BATCH), NTHREADS, SMEM>>>(
        q3, k3, s, R3, R3, R3, SEQ,
        (long)SEQ * R3, (long)SEQ * R3, (long)SEQ * SEQ, scale);
    // K5: softmax rows -> fp16 probs
    softmax_kernel<<<BATCH * SEQ, 256>>>(s, p);
    // K6: out = p @ v  (A=p [S,S] fp16, B=vT rows K-major, batched)
    gemm16_kernel<0><<<dim3(DIM / BN, SEQ / BM, BATCH), NTHREADS, SMEM>>>(
        p, vT, out, SEQ, SEQ, MT, DIM,
        (long)SEQ * SEQ, (long)SEQ, (long)SEQ * DIM, 1.f);
}